// round 15
// baseline (speedup 1.0000x reference)
#include <cuda_runtime.h>
#include <cstdint>

// LineSpectralPairsStabilityCheck: (256, 4096, 33) fp32, 1,048,576 rows.
// Per row: keep [0]; 4 passes of {31-step neighbor-separation scan + clip}.
// R12 structure (single cp.async.bulk in/out per CTA, 1 row/thread,
// conflict-free stride-33 smem) scaled to 256 threads: one 33792B engine
// copy each way. Bigger contiguous staging granules have won at every
// comparison so far (R5>R7, R12>R13-split).

#define W 33
#define THREADS 256
#define ROWS_PER_BLOCK 256
#define TILE_ELEMS (ROWS_PER_BLOCK * W)   // 8448 floats
#define TILE_BYTES (TILE_ELEMS * 4)       // 33792 B (16B-multiple)

__global__ void __launch_bounds__(THREADS)
lsp_stability_kernel(const float* __restrict__ in, float* __restrict__ out)
{
    __shared__ alignas(128) float sm[TILE_ELEMS];
    __shared__ alignas(8) unsigned long long mbar;

    const int t = threadIdx.x;
    const long long base = (long long)blockIdx.x * TILE_ELEMS;

    uint32_t sm_addr, mbar_addr;
    asm("{ .reg .u64 u; cvta.to.shared.u64 u, %1; cvt.u32.u64 %0, u; }"
        : "=r"(sm_addr) : "l"((void*)sm));
    asm("{ .reg .u64 u; cvta.to.shared.u64 u, %1; cvt.u32.u64 %0, u; }"
        : "=r"(mbar_addr) : "l"((void*)&mbar));

    // ---- init mbarrier, then one bulk G->S copy of the whole tile ----
    if (t == 0) {
        asm volatile("mbarrier.init.shared.b64 [%0], 1;" :: "r"(mbar_addr) : "memory");
    }
    __syncthreads();
    if (t == 0) {
        asm volatile("mbarrier.arrive.expect_tx.shared.b64 _, [%0], %1;"
                     :: "r"(mbar_addr), "r"((uint32_t)TILE_BYTES) : "memory");
        asm volatile("cp.async.bulk.shared::cta.global.mbarrier::complete_tx::bytes "
                     "[%0], [%1], %2, [%3];"
                     :: "r"(sm_addr), "l"(in + base), "r"((uint32_t)TILE_BYTES),
                        "r"(mbar_addr) : "memory");
    }
    // ---- wait for the tile (parity 0; one-shot per CTA) ----
    asm volatile(
        "{\n\t"
        ".reg .pred P1;\n\t"
        "WAIT_LOOP_%=:\n\t"
        "mbarrier.try_wait.parity.acquire.cta.shared::cta.b64 P1, [%0], 0, 0x989680;\n\t"
        "@P1 bra.uni WAIT_DONE_%=;\n\t"
        "bra.uni WAIT_LOOP_%=;\n\t"
        "WAIT_DONE_%=:\n\t"
        "}"
        :: "r"(mbar_addr) : "memory");

    // ---- each thread owns one row (stride-33 smem: conflict-free) ----
    // Channel 0 (K) passes through smem untouched.
    const int rbase = t * W;
    float v[W];   // v[0] unused
    #pragma unroll
    for (int i = 1; i < W; i++)
        v[i] = sm[rbase + i];

    const float pi_f  = 3.14159265358979323846f;
    const float min_d = 0.01f * pi_f / 33.0f;   // RATE * pi / (LSP_ORDER + 1)
    const float hi    = pi_f - min_d;

    #pragma unroll
    for (int it = 0; it < 4; it++) {
        // chain per step: u = c + m (FADD) -> s = max(u,0) (FMNMX)
        //              -> c = fma(s, 0.5, nxt) (FFMA); rest off-chain.
        float c = v[1];
        #pragma unroll
        for (int i = 2; i <= 32; i++) {
            float nxt = v[i];
            float m = min_d - nxt;            // off-chain
            float u = c + m;                  // chain
            float s = fmaxf(u, 0.0f);         // chain
            float o = fmaf(s, -0.5f, c);      // off-chain output
            o = fmaxf(o, min_d);
            v[i - 1] = fminf(o, hi);
            c = fmaf(s, 0.5f, nxt);           // chain (carried unclipped)
        }
        v[32] = fminf(fmaxf(c, min_d), hi);
    }

    // ---- write row back to its private smem region ----
    #pragma unroll
    for (int i = 1; i < W; i++)
        sm[rbase + i] = v[i];
    __syncthreads();

    // ---- one bulk S->G copy of the whole tile ----
    if (t == 0) {
        asm volatile("fence.proxy.async.shared::cta;" ::: "memory");
        asm volatile("cp.async.bulk.global.shared::cta.bulk_group [%0], [%1], %2;"
                     :: "l"(out + base), "r"(sm_addr), "r"((uint32_t)TILE_BYTES)
                     : "memory");
        asm volatile("cp.async.bulk.commit_group;" ::: "memory");
        asm volatile("cp.async.bulk.wait_group 0;" ::: "memory");
    }
}

extern "C" void kernel_launch(void* const* d_in, const int* in_sizes, int n_in,
                              void* d_out, int out_size)
{
    const float* in = (const float*)d_in[0];
    float* out = (float*)d_out;

    const int total = in_sizes[0];            // 256*4096*33 = 34,603,008
    const int rows = total / W;               // 1,048,576
    const int blocks = rows / ROWS_PER_BLOCK; // 4096 (exact)

    lsp_stability_kernel<<<blocks, THREADS>>>(in, out);
}

// round 17
// speedup vs baseline: 1.0541x; 1.0541x over previous
#include <cuda_runtime.h>
#include <cstdint>

// LineSpectralPairsStabilityCheck: (256, 4096, 33) fp32, 1,048,576 rows.
// Per row: keep [0]; 4 passes of {31-step neighbor-separation scan + clip}.
// R12 optimum: 128-thread CTA, one 16896B cp.async.bulk in/out (granule
// sweep: 4.2KB=42.3us, 16.9KB=35.97us, 33.8KB=37.3us), 1 row/thread,
// conflict-free stride-33 smem. This round adds L2 evict-first cache hints
// on both bulk copies (zero-reuse 277MB stream; stop L2 churn).

#define W 33
#define THREADS 128
#define ROWS_PER_BLOCK 128
#define TILE_ELEMS (ROWS_PER_BLOCK * W)   // 4224 floats
#define TILE_BYTES (TILE_ELEMS * 4)       // 16896 B (16B-multiple)

__global__ void __launch_bounds__(THREADS)
lsp_stability_kernel(const float* __restrict__ in, float* __restrict__ out)
{
    __shared__ alignas(128) float sm[TILE_ELEMS];
    __shared__ alignas(8) unsigned long long mbar;

    const int t = threadIdx.x;
    const long long base = (long long)blockIdx.x * TILE_ELEMS;

    uint32_t sm_addr, mbar_addr;
    asm("{ .reg .u64 u; cvta.to.shared.u64 u, %1; cvt.u32.u64 %0, u; }"
        : "=r"(sm_addr) : "l"((void*)sm));
    asm("{ .reg .u64 u; cvta.to.shared.u64 u, %1; cvt.u32.u64 %0, u; }"
        : "=r"(mbar_addr) : "l"((void*)&mbar));

    // ---- init mbarrier, then one bulk G->S copy (evict-first hint) ----
    if (t == 0) {
        asm volatile("mbarrier.init.shared.b64 [%0], 1;" :: "r"(mbar_addr) : "memory");
    }
    __syncthreads();
    if (t == 0) {
        asm volatile("mbarrier.arrive.expect_tx.shared.b64 _, [%0], %1;"
                     :: "r"(mbar_addr), "r"((uint32_t)TILE_BYTES) : "memory");
        asm volatile(
            "{\n\t"
            ".reg .b64 pol;\n\t"
            "createpolicy.fractional.L2::evict_first.b64 pol, 1.0;\n\t"
            "cp.async.bulk.shared::cta.global.mbarrier::complete_tx::bytes.L2::cache_hint "
            "[%0], [%1], %2, [%3], pol;\n\t"
            "}"
            :: "r"(sm_addr), "l"(in + base), "r"((uint32_t)TILE_BYTES),
               "r"(mbar_addr) : "memory");
    }
    // ---- wait for the tile (parity 0; one-shot per CTA) ----
    asm volatile(
        "{\n\t"
        ".reg .pred P1;\n\t"
        "WAIT_LOOP_%=:\n\t"
        "mbarrier.try_wait.parity.acquire.cta.shared::cta.b64 P1, [%0], 0, 0x989680;\n\t"
        "@P1 bra.uni WAIT_DONE_%=;\n\t"
        "bra.uni WAIT_LOOP_%=;\n\t"
        "WAIT_DONE_%=:\n\t"
        "}"
        :: "r"(mbar_addr) : "memory");

    // ---- each thread owns one row (stride-33 smem: conflict-free) ----
    // Channel 0 (K) passes through smem untouched.
    const int rbase = t * W;
    float v[W];   // v[0] unused
    #pragma unroll
    for (int i = 1; i < W; i++)
        v[i] = sm[rbase + i];

    const float pi_f  = 3.14159265358979323846f;
    const float min_d = 0.01f * pi_f / 33.0f;   // RATE * pi / (LSP_ORDER + 1)
    const float hi    = pi_f - min_d;

    #pragma unroll
    for (int it = 0; it < 4; it++) {
        // chain per step: u = c + m (FADD) -> s = max(u,0) (FMNMX)
        //              -> c = fma(s, 0.5, nxt) (FFMA); rest off-chain.
        float c = v[1];
        #pragma unroll
        for (int i = 2; i <= 32; i++) {
            float nxt = v[i];
            float m = min_d - nxt;            // off-chain
            float u = c + m;                  // chain
            float s = fmaxf(u, 0.0f);         // chain
            float o = fmaf(s, -0.5f, c);      // off-chain output
            o = fmaxf(o, min_d);
            v[i - 1] = fminf(o, hi);
            c = fmaf(s, 0.5f, nxt);           // chain (carried unclipped)
        }
        v[32] = fminf(fmaxf(c, min_d), hi);
    }

    // ---- write row back to its private smem region ----
    #pragma unroll
    for (int i = 1; i < W; i++)
        sm[rbase + i] = v[i];
    __syncthreads();

    // ---- one bulk S->G copy of the whole tile (evict-first hint) ----
    if (t == 0) {
        asm volatile("fence.proxy.async.shared::cta;" ::: "memory");
        asm volatile(
            "{\n\t"
            ".reg .b64 pol;\n\t"
            "createpolicy.fractional.L2::evict_first.b64 pol, 1.0;\n\t"
            "cp.async.bulk.global.shared::cta.bulk_group.L2::cache_hint "
            "[%0], [%1], %2, pol;\n\t"
            "}"
            :: "l"(out + base), "r"(sm_addr), "r"((uint32_t)TILE_BYTES)
            : "memory");
        asm volatile("cp.async.bulk.commit_group;" ::: "memory");
        asm volatile("cp.async.bulk.wait_group 0;" ::: "memory");
    }
}

extern "C" void kernel_launch(void* const* d_in, const int* in_sizes, int n_in,
                              void* d_out, int out_size)
{
    const float* in = (const float*)d_in[0];
    float* out = (float*)d_out;

    const int total = in_sizes[0];            // 256*4096*33 = 34,603,008
    const int rows = total / W;               // 1,048,576
    const int blocks = rows / ROWS_PER_BLOCK; // 8192 (exact)

    lsp_stability_kernel<<<blocks, THREADS>>>(in, out);
}